// round 4
// baseline (speedup 1.0000x reference)
#include <cuda_runtime.h>
#include <cuda_fp16.h>
#include <cstdint>

#define HEADS 4
#define DIM_HEAD 32
#define NPOS 4096
#define BATCH 4
#define CDIM 256
#define HIDDEN 128
#define SCALE 0.17677669529663687f  // 32^-0.5

// Scratch (allocation-free rule: __device__ globals)
__device__ __align__(16) float g_q[BATCH * HEADS * NPOS * DIM_HEAD];
__device__ __align__(16) float g_k[BATCH * HEADS * NPOS * DIM_HEAD];
__device__ __align__(16) float g_v[BATCH * HEADS * NPOS * DIM_HEAD];
__device__ __align__(16) float g_attn[BATCH * NPOS * HIDDEN];

// ---------------------------------------------------------------------------
// mma helpers
// ---------------------------------------------------------------------------
__device__ __forceinline__ uint32_t f2tf32(float x) {
    uint32_t u;
    asm("cvt.rna.tf32.f32 %0, %1;" : "=r"(u) : "f"(x));
    return u;
}

__device__ __forceinline__ void mma_tf32(float (&c)[4],
                                         uint32_t a0, uint32_t a1, uint32_t a2, uint32_t a3,
                                         uint32_t b0, uint32_t b1) {
    asm volatile(
        "mma.sync.aligned.m16n8k8.row.col.f32.tf32.tf32.f32 "
        "{%0,%1,%2,%3},{%4,%5,%6,%7},{%8,%9},{%0,%1,%2,%3};\n"
        : "+f"(c[0]), "+f"(c[1]), "+f"(c[2]), "+f"(c[3])
        : "r"(a0), "r"(a1), "r"(a2), "r"(a3), "r"(b0), "r"(b1));
}

__device__ __forceinline__ void mma_f16(float (&c)[4],
                                        uint32_t a0, uint32_t a1, uint32_t a2, uint32_t a3,
                                        uint32_t b0, uint32_t b1) {
    asm volatile(
        "mma.sync.aligned.m16n8k16.row.col.f32.f16.f16.f32 "
        "{%0,%1,%2,%3},{%4,%5,%6,%7},{%8,%9},{%0,%1,%2,%3};\n"
        : "+f"(c[0]), "+f"(c[1]), "+f"(c[2]), "+f"(c[3])
        : "r"(a0), "r"(a1), "r"(a2), "r"(a3), "r"(b0), "r"(b1));
}

__device__ __forceinline__ uint32_t pack_h2(float lo, float hi) {
    __half2 h = __floats2half2_rn(lo, hi);
    return *reinterpret_cast<uint32_t*>(&h);
}

// ---------------------------------------------------------------------------
// Templated tf32-MMA GEMM for the two 1x1-conv projections.
//   C[o][p] = sum_k A[o][k] * B(k, p)   (per batch b)
// Block: 8 warps, tile 64(O) x 128(P), K-step 16.
// BROWMAJOR_K: B stored [k][p] (the input x). Else B = g_attn [p][k].
// QKV_EPI: scatter into g_q/g_k/g_v; else bias + write y.
// ---------------------------------------------------------------------------
template <int KDIM, bool BROWMAJOR_K, bool QKV_EPI>
__global__ __launch_bounds__(256) void gemm_tf32(const float* __restrict__ A,
                                                 const float* __restrict__ B,
                                                 const float* __restrict__ bias,
                                                 float* __restrict__ y) {
    __shared__ __align__(16) float As[16][72];
    __shared__ __align__(16) float Bs[16][136];
    const int b  = blockIdx.z;
    const int o0 = blockIdx.y * 64;
    const int p0 = blockIdx.x * 128;
    const int tid  = threadIdx.x;
    const int warp = tid >> 5, lane = tid & 31;
    const int g = lane >> 2, tg = lane & 3;
    const int wm = warp & 3, wn = warp >> 2;
    const int om = wm * 16, on = wn * 64;

    const float* Bb;
    if constexpr (BROWMAJOR_K) Bb = B + (size_t)b * KDIM * NPOS;
    else                       Bb = g_attn + (size_t)b * NPOS * HIDDEN;

    float C[8][4] = {};

    for (int k0 = 0; k0 < KDIM; k0 += 16) {
        {   // A tile -> As[k][o] (transposed), tf32 bits
            int oo = tid & 63, kq = tid >> 6;   // kq 0..3
            float4 wv = *(const float4*)&A[(size_t)(o0 + oo) * KDIM + k0 + kq * 4];
            As[kq * 4 + 0][oo] = __uint_as_float(f2tf32(wv.x));
            As[kq * 4 + 1][oo] = __uint_as_float(f2tf32(wv.y));
            As[kq * 4 + 2][oo] = __uint_as_float(f2tf32(wv.z));
            As[kq * 4 + 3][oo] = __uint_as_float(f2tf32(wv.w));
        }
        if constexpr (BROWMAJOR_K) {   // x: [k][p], coalesced float4 rows
            int kk = tid >> 5, pq = tid & 31;
            #pragma unroll
            for (int e = 0; e < 2; e++) {
                float4 xv = *(const float4*)&Bb[(size_t)(k0 + kk + e * 8) * NPOS + p0 + pq * 4];
                float4 tv;
                tv.x = __uint_as_float(f2tf32(xv.x));
                tv.y = __uint_as_float(f2tf32(xv.y));
                tv.z = __uint_as_float(f2tf32(xv.z));
                tv.w = __uint_as_float(f2tf32(xv.w));
                *(float4*)&Bs[kk + e * 8][pq * 4] = tv;
            }
        } else {   // g_attn: [p][k] -> transpose into Bs[k][p]
            int pp = tid & 127, kq = tid >> 7;  // kq 0..1
            #pragma unroll
            for (int e = 0; e < 2; e++) {
                int kq4 = (kq + 2 * e) * 4;
                float4 av = *(const float4*)&Bb[(size_t)(p0 + pp) * KDIM + k0 + kq4];
                Bs[kq4 + 0][pp] = __uint_as_float(f2tf32(av.x));
                Bs[kq4 + 1][pp] = __uint_as_float(f2tf32(av.y));
                Bs[kq4 + 2][pp] = __uint_as_float(f2tf32(av.z));
                Bs[kq4 + 3][pp] = __uint_as_float(f2tf32(av.w));
            }
        }
        __syncthreads();

        #pragma unroll
        for (int h = 0; h < 2; h++) {
            uint32_t a0 = __float_as_uint(As[h * 8 + tg][om + g]);
            uint32_t a1 = __float_as_uint(As[h * 8 + tg][om + g + 8]);
            uint32_t a2 = __float_as_uint(As[h * 8 + tg + 4][om + g]);
            uint32_t a3 = __float_as_uint(As[h * 8 + tg + 4][om + g + 8]);
            #pragma unroll
            for (int nt = 0; nt < 8; nt++) {
                int n = on + nt * 8 + g;
                uint32_t b0 = __float_as_uint(Bs[h * 8 + tg][n]);
                uint32_t b1 = __float_as_uint(Bs[h * 8 + tg + 4][n]);
                mma_tf32(C[nt], a0, a1, a2, a3, b0, b1);
            }
        }
        __syncthreads();
    }

    if constexpr (QKV_EPI) {
        #pragma unroll
        for (int h = 0; h < 2; h++) {
            int row = o0 + om + g + h * 8;
            int part = row >> 7, oc = row & 127;
            int head = oc >> 5, d = oc & 31;
            float* dst = (part == 0) ? g_q : (part == 1) ? g_k : g_v;
            float sc = (part == 0) ? SCALE : 1.0f;
            size_t base = (((size_t)b * HEADS + head) * NPOS) * DIM_HEAD + d;
            #pragma unroll
            for (int nt = 0; nt < 8; nt++) {
                int p = p0 + on + nt * 8 + 2 * tg;
                dst[base + (size_t)p * DIM_HEAD]       = C[nt][2 * h]     * sc;
                dst[base + (size_t)(p + 1) * DIM_HEAD] = C[nt][2 * h + 1] * sc;
            }
        }
    } else {
        #pragma unroll
        for (int h = 0; h < 2; h++) {
            int row = o0 + om + g + h * 8;
            float bb = bias[row];
            #pragma unroll
            for (int nt = 0; nt < 8; nt++) {
                int p = p0 + on + nt * 8 + 2 * tg;
                *(float2*)&y[((size_t)b * CDIM + row) * NPOS + p] =
                    make_float2(C[nt][2 * h] + bb, C[nt][2 * h + 1] + bb);
            }
        }
    }
}

// ---------------------------------------------------------------------------
// Flash attention: QK^T in tf32 mma, PV in fp16 mma (FA-2 register identity:
// S C-fragment == fp16 A-fragment, zero shuffles). K/V double-buffered.
// Block = 8 warps, Q tile = 128 rows (16/warp). Key tile = 64.
// ---------------------------------------------------------------------------
__global__ __launch_bounds__(256) void attn_mma_kernel() {
    __shared__ __align__(16) float Ks[2][64][36];
    __shared__ __align__(16) __half Vt[2][32][72];   // [d][key], stride 72

    const int bh = blockIdx.y;
    const int q0 = blockIdx.x * 128;
    const int tid = threadIdx.x;
    const int warp = tid >> 5, lane = tid & 31;
    const int g = lane >> 2, tg = lane & 3;
    const unsigned FULL = 0xffffffffu;

    const float* Qg = g_q + (size_t)bh * NPOS * DIM_HEAD;
    const float* Kg = g_k + (size_t)bh * NPOS * DIM_HEAD;
    const float* Vg = g_v + (size_t)bh * NPOS * DIM_HEAD;

    // Q fragments (A-layout, tf32)
    const int qrow0 = q0 + warp * 16 + g;
    uint32_t Qf[4][4];
    #pragma unroll
    for (int kt = 0; kt < 4; kt++) {
        int c = kt * 8 + tg;
        Qf[kt][0] = f2tf32(Qg[(size_t)qrow0 * DIM_HEAD + c]);
        Qf[kt][1] = f2tf32(Qg[(size_t)(qrow0 + 8) * DIM_HEAD + c]);
        Qf[kt][2] = f2tf32(Qg[(size_t)qrow0 * DIM_HEAD + c + 4]);
        Qf[kt][3] = f2tf32(Qg[(size_t)(qrow0 + 8) * DIM_HEAD + c + 4]);
    }

    const int lr  = tid >> 3;          // load row 0..31 (+32 for e=1)
    const int ld4 = (tid & 7) * 4;     // load d offset

    float4 pk[2], pv[2];
    // prologue: issue + commit tile 0 into buffer 0
    #pragma unroll
    for (int e = 0; e < 2; e++) {
        int r = lr + e * 32;
        pk[e] = *(const float4*)&Kg[(size_t)r * DIM_HEAD + ld4];
        pv[e] = *(const float4*)&Vg[(size_t)r * DIM_HEAD + ld4];
    }
    #pragma unroll
    for (int e = 0; e < 2; e++) {
        int r = lr + e * 32;
        Ks[0][r][ld4 + 0] = __uint_as_float(f2tf32(pk[e].x));
        Ks[0][r][ld4 + 1] = __uint_as_float(f2tf32(pk[e].y));
        Ks[0][r][ld4 + 2] = __uint_as_float(f2tf32(pk[e].z));
        Ks[0][r][ld4 + 3] = __uint_as_float(f2tf32(pk[e].w));
        Vt[0][ld4 + 0][r] = __float2half_rn(pv[e].x);
        Vt[0][ld4 + 1][r] = __float2half_rn(pv[e].y);
        Vt[0][ld4 + 2][r] = __float2half_rn(pv[e].z);
        Vt[0][ld4 + 3][r] = __float2half_rn(pv[e].w);
    }
    __syncthreads();

    float O[4][4] = {};
    float m0 = -1e30f, m1 = -1e30f, l0 = 0.f, l1 = 0.f;

    for (int t = 0; t < NPOS; t += 64) {
        const int s = (t >> 6) & 1;
        const bool more = (t + 64) < NPOS;
        if (more) {   // issue next tile's loads (latency overlapped with compute)
            #pragma unroll
            for (int e = 0; e < 2; e++) {
                int r = t + 64 + lr + e * 32;
                pk[e] = *(const float4*)&Kg[(size_t)r * DIM_HEAD + ld4];
                pv[e] = *(const float4*)&Vg[(size_t)r * DIM_HEAD + ld4];
            }
        }

        // ---- S = Q K^T (tf32): 8 n-tiles x 4 k-chunks
        float S[8][4];
        #pragma unroll
        for (int nt = 0; nt < 8; nt++) {
            S[nt][0] = S[nt][1] = S[nt][2] = S[nt][3] = 0.f;
            const int key = nt * 8 + g;
            #pragma unroll
            for (int kt = 0; kt < 4; kt++) {
                const int d = kt * 8 + tg;
                uint32_t b0 = __float_as_uint(Ks[s][key][d]);
                uint32_t b1 = __float_as_uint(Ks[s][key][d + 4]);
                mma_tf32(S[nt], Qf[kt][0], Qf[kt][1], Qf[kt][2], Qf[kt][3], b0, b1);
            }
        }

        // ---- online softmax
        float rmax0 = -1e30f, rmax1 = -1e30f;
        #pragma unroll
        for (int nt = 0; nt < 8; nt++) {
            rmax0 = fmaxf(rmax0, fmaxf(S[nt][0], S[nt][1]));
            rmax1 = fmaxf(rmax1, fmaxf(S[nt][2], S[nt][3]));
        }
        rmax0 = fmaxf(rmax0, __shfl_xor_sync(FULL, rmax0, 1));
        rmax0 = fmaxf(rmax0, __shfl_xor_sync(FULL, rmax0, 2));
        rmax1 = fmaxf(rmax1, __shfl_xor_sync(FULL, rmax1, 1));
        rmax1 = fmaxf(rmax1, __shfl_xor_sync(FULL, rmax1, 2));

        float mn0 = fmaxf(m0, rmax0), mn1 = fmaxf(m1, rmax1);
        float alpha0 = __expf(m0 - mn0), alpha1 = __expf(m1 - mn1);
        m0 = mn0; m1 = mn1;

        float rs0 = 0.f, rs1 = 0.f;
        #pragma unroll
        for (int nt = 0; nt < 8; nt++) {
            S[nt][0] = __expf(S[nt][0] - mn0);
            S[nt][1] = __expf(S[nt][1] - mn0);
            S[nt][2] = __expf(S[nt][2] - mn1);
            S[nt][3] = __expf(S[nt][3] - mn1);
            rs0 += S[nt][0] + S[nt][1];
            rs1 += S[nt][2] + S[nt][3];
        }
        rs0 += __shfl_xor_sync(FULL, rs0, 1);
        rs0 += __shfl_xor_sync(FULL, rs0, 2);
        rs1 += __shfl_xor_sync(FULL, rs1, 1);
        rs1 += __shfl_xor_sync(FULL, rs1, 2);
        l0 = l0 * alpha0 + rs0;
        l1 = l1 * alpha1 + rs1;

        #pragma unroll
        for (int nt = 0; nt < 4; nt++) {
            O[nt][0] *= alpha0; O[nt][1] *= alpha0;
            O[nt][2] *= alpha1; O[nt][3] *= alpha1;
        }

        // ---- O += P V  (fp16 m16n8k16; S C-frag == A-frag, no shuffles)
        #pragma unroll
        for (int kc = 0; kc < 4; kc++) {
            uint32_t a0 = pack_h2(S[2 * kc][0],     S[2 * kc][1]);
            uint32_t a1 = pack_h2(S[2 * kc][2],     S[2 * kc][3]);
            uint32_t a2 = pack_h2(S[2 * kc + 1][0], S[2 * kc + 1][1]);
            uint32_t a3 = pack_h2(S[2 * kc + 1][2], S[2 * kc + 1][3]);
            #pragma unroll
            for (int nt = 0; nt < 4; nt++) {
                const int d = nt * 8 + g;
                uint32_t b0 = *(const uint32_t*)&Vt[s][d][kc * 16 + 2 * tg];
                uint32_t b1 = *(const uint32_t*)&Vt[s][d][kc * 16 + 8 + 2 * tg];
                mma_f16(O[nt], a0, a1, a2, a3, b0, b1);
            }
        }

        __syncthreads();   // all warps done reading buffer s^1 (two iters ago)
        if (more) {        // commit prefetched tile into the other buffer
            const int sn = s ^ 1;
            #pragma unroll
            for (int e = 0; e < 2; e++) {
                int r = lr + e * 32;
                Ks[sn][r][ld4 + 0] = __uint_as_float(f2tf32(pk[e].x));
                Ks[sn][r][ld4 + 1] = __uint_as_float(f2tf32(pk[e].y));
                Ks[sn][r][ld4 + 2] = __uint_as_float(f2tf32(pk[e].z));
                Ks[sn][r][ld4 + 3] = __uint_as_float(f2tf32(pk[e].w));
                Vt[sn][ld4 + 0][r] = __float2half_rn(pv[e].x);
                Vt[sn][ld4 + 1][r] = __float2half_rn(pv[e].y);
                Vt[sn][ld4 + 2][r] = __float2half_rn(pv[e].z);
                Vt[sn][ld4 + 3][r] = __float2half_rn(pv[e].w);
            }
        }
        __syncthreads();
    }

    // ---- epilogue: normalize, write g_attn[b][pos][head*32 + d]
    const int b = bh >> 2, head = bh & 3;
    const float inv0 = 1.f / l0, inv1 = 1.f / l1;
    #pragma unroll
    for (int nt = 0; nt < 4; nt++) {
        int col = head * 32 + nt * 8 + 2 * tg;
        float2 w0 = make_float2(O[nt][0] * inv0, O[nt][1] * inv0);
        float2 w1 = make_float2(O[nt][2] * inv1, O[nt][3] * inv1);
        *(float2*)&g_attn[((size_t)b * NPOS + qrow0) * HIDDEN + col] = w0;
        *(float2*)&g_attn[((size_t)b * NPOS + qrow0 + 8) * HIDDEN + col] = w1;
    }
}

// ---------------------------------------------------------------------------
extern "C" void kernel_launch(void* const* d_in, const int* in_sizes, int n_in,
                              void* d_out, int out_size) {
    const float* x     = (const float*)d_in[0];
    const float* w_qkv = (const float*)d_in[1];
    const float* w_out = (const float*)d_in[2];
    const float* b_out = (const float*)d_in[3];
    float* y = (float*)d_out;

    gemm_tf32<CDIM, true, true><<<dim3(NPOS / 128, 384 / 64, BATCH), 256>>>(
        w_qkv, x, nullptr, nullptr);
    attn_mma_kernel<<<dim3(NPOS / 128, BATCH * HEADS), 256>>>();
    gemm_tf32<HIDDEN, false, false><<<dim3(NPOS / 128, CDIM / 64, BATCH), 256>>>(
        w_out, nullptr, b_out, y);
}

// round 5
// speedup vs baseline: 2.0082x; 2.0082x over previous
#include <cuda_runtime.h>
#include <cuda_fp16.h>
#include <cstdint>

#define HEADS 4
#define DIM_HEAD 32
#define NPOS 4096
#define BATCH 4
#define CDIM 256
#define HIDDEN 128
#define SCALE 0.17677669529663687f  // 32^-0.5

// Scratch (allocation-free rule: __device__ globals)
__device__ __align__(16) __half g_qh[BATCH * HEADS * NPOS * DIM_HEAD];
__device__ __align__(16) __half g_kh[BATCH * HEADS * NPOS * DIM_HEAD];
__device__ __align__(16) __half g_vh[BATCH * HEADS * NPOS * DIM_HEAD];
__device__ __align__(16) float  g_attn[BATCH * NPOS * HIDDEN];

// ---------------------------------------------------------------------------
// mma / ldmatrix / cp.async helpers
// ---------------------------------------------------------------------------
__device__ __forceinline__ uint32_t f2tf32(float x) {
    uint32_t u;
    asm("cvt.rna.tf32.f32 %0, %1;" : "=r"(u) : "f"(x));
    return u;
}

__device__ __forceinline__ void mma_tf32(float (&c)[4],
                                         uint32_t a0, uint32_t a1, uint32_t a2, uint32_t a3,
                                         uint32_t b0, uint32_t b1) {
    asm volatile(
        "mma.sync.aligned.m16n8k8.row.col.f32.tf32.tf32.f32 "
        "{%0,%1,%2,%3},{%4,%5,%6,%7},{%8,%9},{%0,%1,%2,%3};\n"
        : "+f"(c[0]), "+f"(c[1]), "+f"(c[2]), "+f"(c[3])
        : "r"(a0), "r"(a1), "r"(a2), "r"(a3), "r"(b0), "r"(b1));
}

__device__ __forceinline__ void mma_f16(float (&c)[4],
                                        uint32_t a0, uint32_t a1, uint32_t a2, uint32_t a3,
                                        uint32_t b0, uint32_t b1) {
    asm volatile(
        "mma.sync.aligned.m16n8k16.row.col.f32.f16.f16.f32 "
        "{%0,%1,%2,%3},{%4,%5,%6,%7},{%8,%9},{%0,%1,%2,%3};\n"
        : "+f"(c[0]), "+f"(c[1]), "+f"(c[2]), "+f"(c[3])
        : "r"(a0), "r"(a1), "r"(a2), "r"(a3), "r"(b0), "r"(b1));
}

__device__ __forceinline__ uint32_t pack_h2(float lo, float hi) {
    __half2 h = __floats2half2_rn(lo, hi);
    return *reinterpret_cast<uint32_t*>(&h);
}

__device__ __forceinline__ void ldsm_x4_t(uint32_t& r0, uint32_t& r1,
                                          uint32_t& r2, uint32_t& r3, uint32_t addr) {
    asm volatile("ldmatrix.sync.aligned.m8n8.x4.trans.shared.b16 {%0,%1,%2,%3}, [%4];"
                 : "=r"(r0), "=r"(r1), "=r"(r2), "=r"(r3) : "r"(addr));
}

__device__ __forceinline__ void cp16(uint32_t saddr, const void* gaddr) {
    asm volatile("cp.async.ca.shared.global [%0], [%1], 16;" :: "r"(saddr), "l"(gaddr));
}
__device__ __forceinline__ void cp_commit() { asm volatile("cp.async.commit_group;"); }
__device__ __forceinline__ void cp_wait1() { asm volatile("cp.async.wait_group 1;"); }
__device__ __forceinline__ void cp_wait0() { asm volatile("cp.async.wait_group 0;"); }

// ---------------------------------------------------------------------------
// Templated tf32-MMA GEMM for the two 1x1-conv projections.
//   C[o][p] = sum_k A[o][k] * B(k, p)   (per batch b)
// Block: 8 warps, tile 64(O) x 128(P), K-step 16.
// ---------------------------------------------------------------------------
template <int KDIM, bool BROWMAJOR_K, bool QKV_EPI>
__global__ __launch_bounds__(256) void gemm_tf32(const float* __restrict__ A,
                                                 const float* __restrict__ B,
                                                 const float* __restrict__ bias,
                                                 float* __restrict__ y) {
    __shared__ __align__(16) float As[16][72];
    __shared__ __align__(16) float Bs[16][136];
    const int b  = blockIdx.z;
    const int o0 = blockIdx.y * 64;
    const int p0 = blockIdx.x * 128;
    const int tid  = threadIdx.x;
    const int warp = tid >> 5, lane = tid & 31;
    const int g = lane >> 2, tg = lane & 3;
    const int wm = warp & 3, wn = warp >> 2;
    const int om = wm * 16, on = wn * 64;

    const float* Bb;
    if constexpr (BROWMAJOR_K) Bb = B + (size_t)b * KDIM * NPOS;
    else                       Bb = g_attn + (size_t)b * NPOS * HIDDEN;

    float C[8][4] = {};

    for (int k0 = 0; k0 < KDIM; k0 += 16) {
        {   // A tile -> As[k][o] (transposed), tf32 bits
            int oo = tid & 63, kq = tid >> 6;
            float4 wv = *(const float4*)&A[(size_t)(o0 + oo) * KDIM + k0 + kq * 4];
            As[kq * 4 + 0][oo] = __uint_as_float(f2tf32(wv.x));
            As[kq * 4 + 1][oo] = __uint_as_float(f2tf32(wv.y));
            As[kq * 4 + 2][oo] = __uint_as_float(f2tf32(wv.z));
            As[kq * 4 + 3][oo] = __uint_as_float(f2tf32(wv.w));
        }
        if constexpr (BROWMAJOR_K) {
            int kk = tid >> 5, pq = tid & 31;
            #pragma unroll
            for (int e = 0; e < 2; e++) {
                float4 xv = *(const float4*)&Bb[(size_t)(k0 + kk + e * 8) * NPOS + p0 + pq * 4];
                float4 tv;
                tv.x = __uint_as_float(f2tf32(xv.x));
                tv.y = __uint_as_float(f2tf32(xv.y));
                tv.z = __uint_as_float(f2tf32(xv.z));
                tv.w = __uint_as_float(f2tf32(xv.w));
                *(float4*)&Bs[kk + e * 8][pq * 4] = tv;
            }
        } else {
            int pp = tid & 127, kq = tid >> 7;
            #pragma unroll
            for (int e = 0; e < 2; e++) {
                int kq4 = (kq + 2 * e) * 4;
                float4 av = *(const float4*)&Bb[(size_t)(p0 + pp) * KDIM + k0 + kq4];
                Bs[kq4 + 0][pp] = __uint_as_float(f2tf32(av.x));
                Bs[kq4 + 1][pp] = __uint_as_float(f2tf32(av.y));
                Bs[kq4 + 2][pp] = __uint_as_float(f2tf32(av.z));
                Bs[kq4 + 3][pp] = __uint_as_float(f2tf32(av.w));
            }
        }
        __syncthreads();

        #pragma unroll
        for (int h = 0; h < 2; h++) {
            uint32_t a0 = __float_as_uint(As[h * 8 + tg][om + g]);
            uint32_t a1 = __float_as_uint(As[h * 8 + tg][om + g + 8]);
            uint32_t a2 = __float_as_uint(As[h * 8 + tg + 4][om + g]);
            uint32_t a3 = __float_as_uint(As[h * 8 + tg + 4][om + g + 8]);
            #pragma unroll
            for (int nt = 0; nt < 8; nt++) {
                int n = on + nt * 8 + g;
                uint32_t b0 = __float_as_uint(Bs[h * 8 + tg][n]);
                uint32_t b1 = __float_as_uint(Bs[h * 8 + tg + 4][n]);
                mma_tf32(C[nt], a0, a1, a2, a3, b0, b1);
            }
        }
        __syncthreads();
    }

    if constexpr (QKV_EPI) {
        // Stage tile as half in smem, then coalesced 16B stores to g_{q,k,v}h.
        __shared__ __align__(16) __half Stage[128][72];
        const float sc = (o0 < 128) ? SCALE : 1.0f;
        #pragma unroll
        for (int h = 0; h < 2; h++) {
            int orow = om + g + h * 8;
            #pragma unroll
            for (int nt = 0; nt < 8; nt++) {
                int p = on + nt * 8 + 2 * tg;
                Stage[p][orow]     = __float2half_rn(C[nt][2 * h] * sc);
                Stage[p + 1][orow] = __float2half_rn(C[nt][2 * h + 1] * sc);
            }
        }
        __syncthreads();
        int pp = tid >> 1, o_base = (tid & 1) * 32;
        int row0 = o0 + o_base;                 // global output-channel of chunk
        int part = row0 >> 7, head = (row0 & 127) >> 5;
        __half* dst = (part == 0) ? g_qh : (part == 1) ? g_kh : g_vh;
        size_t base = (((size_t)b * HEADS + head) * NPOS + p0 + pp) * DIM_HEAD;
        #pragma unroll
        for (int j = 0; j < 4; j++)
            *(uint4*)&dst[base + j * 8] = *(uint4*)&Stage[pp][o_base + j * 8];
    } else {
        #pragma unroll
        for (int h = 0; h < 2; h++) {
            int row = o0 + om + g + h * 8;
            float bb = bias[row];
            #pragma unroll
            for (int nt = 0; nt < 8; nt++) {
                int p = p0 + on + nt * 8 + 2 * tg;
                *(float2*)&y[((size_t)b * CDIM + row) * NPOS + p] =
                    make_float2(C[nt][2 * h] + bb, C[nt][2 * h + 1] + bb);
            }
        }
    }
}

// ---------------------------------------------------------------------------
// Flash attention, all-fp16 MMA path.
// Block = 8 warps, Q tile = 128 rows (16/warp). Key tile = 64.
// QK^T: fp16 m16n8k16, K b-frags direct u32 smem loads (conflict-free).
// PV:   fp16 m16n8k16, S C-frag == A-frag identity, V b-frags via ldmatrix.trans.
// K/V stream via cp.async double-buffer; zero conversions in the loop.
// ---------------------------------------------------------------------------
#define KVSTR 40   // halves per row (80B, 16B-aligned rows for ldmatrix)

__global__ __launch_bounds__(256) void attn_mma_kernel() {
    __shared__ __align__(16) __half Ksm[2][64][KVSTR];
    __shared__ __align__(16) __half Vsm[2][64][KVSTR];

    const int bh = blockIdx.y;
    const int q0 = blockIdx.x * 128;
    const int tid = threadIdx.x;
    const int warp = tid >> 5, lane = tid & 31;
    const int g = lane >> 2, tg = lane & 3;
    const unsigned FULL = 0xffffffffu;

    const __half* Qh = g_qh + (size_t)bh * NPOS * DIM_HEAD;
    const __half* Kh = g_kh + (size_t)bh * NPOS * DIM_HEAD;
    const __half* Vh = g_vh + (size_t)bh * NPOS * DIM_HEAD;

    // Q A-fragments (fp16 m16n8k16): 2 k-chunks of 16
    const int qrow0 = q0 + warp * 16 + g;
    uint32_t Qf[2][4];
    #pragma unroll
    for (int kc = 0; kc < 2; kc++) {
        int c = kc * 16 + 2 * tg;
        Qf[kc][0] = *(const uint32_t*)&Qh[(size_t)qrow0 * DIM_HEAD + c];
        Qf[kc][1] = *(const uint32_t*)&Qh[(size_t)(qrow0 + 8) * DIM_HEAD + c];
        Qf[kc][2] = *(const uint32_t*)&Qh[(size_t)qrow0 * DIM_HEAD + c + 8];
        Qf[kc][3] = *(const uint32_t*)&Qh[(size_t)(qrow0 + 8) * DIM_HEAD + c + 8];
    }

    // cp.async tile loader: thread -> (row, 8-half chunk)
    const int kr  = tid >> 2;
    const int kc8 = (tid & 3) * 8;
    uint32_t kdst[2], vdst[2];
    #pragma unroll
    for (int s = 0; s < 2; s++) {
        kdst[s] = (uint32_t)__cvta_generic_to_shared(&Ksm[s][kr][kc8]);
        vdst[s] = (uint32_t)__cvta_generic_to_shared(&Vsm[s][kr][kc8]);
    }

    // prologue: tile 0 -> buffer 0
    cp16(kdst[0], Kh + (size_t)kr * DIM_HEAD + kc8);
    cp16(vdst[0], Vh + (size_t)kr * DIM_HEAD + kc8);
    cp_commit();

    float O[4][4] = {};
    float m0 = -1e30f, m1 = -1e30f, l0 = 0.f, l1 = 0.f;

    for (int it = 0; it < NPOS / 64; it++) {
        const int s = it & 1;
        if (it + 1 < NPOS / 64) {
            size_t rb = (size_t)(it + 1) * 64 + kr;
            cp16(kdst[s ^ 1], Kh + rb * DIM_HEAD + kc8);
            cp16(vdst[s ^ 1], Vh + rb * DIM_HEAD + kc8);
            cp_commit();
            cp_wait1();
        } else {
            cp_wait0();
        }
        __syncthreads();

        // ---- S = Q K^T (fp16): 2 k-chunks x 8 n-tiles
        float S[8][4];
        #pragma unroll
        for (int nt = 0; nt < 8; nt++)
            S[nt][0] = S[nt][1] = S[nt][2] = S[nt][3] = 0.f;
        #pragma unroll
        for (int kc = 0; kc < 2; kc++) {
            #pragma unroll
            for (int nt = 0; nt < 8; nt++) {
                const __half* kp = &Ksm[s][nt * 8 + g][kc * 16 + 2 * tg];
                uint32_t b0 = *(const uint32_t*)kp;
                uint32_t b1 = *(const uint32_t*)(kp + 8);
                mma_f16(S[nt], Qf[kc][0], Qf[kc][1], Qf[kc][2], Qf[kc][3], b0, b1);
            }
        }

        // ---- online softmax
        float rmax0 = -1e30f, rmax1 = -1e30f;
        #pragma unroll
        for (int nt = 0; nt < 8; nt++) {
            rmax0 = fmaxf(rmax0, fmaxf(S[nt][0], S[nt][1]));
            rmax1 = fmaxf(rmax1, fmaxf(S[nt][2], S[nt][3]));
        }
        rmax0 = fmaxf(rmax0, __shfl_xor_sync(FULL, rmax0, 1));
        rmax0 = fmaxf(rmax0, __shfl_xor_sync(FULL, rmax0, 2));
        rmax1 = fmaxf(rmax1, __shfl_xor_sync(FULL, rmax1, 1));
        rmax1 = fmaxf(rmax1, __shfl_xor_sync(FULL, rmax1, 2));

        float mn0 = fmaxf(m0, rmax0), mn1 = fmaxf(m1, rmax1);
        float alpha0 = __expf(m0 - mn0), alpha1 = __expf(m1 - mn1);
        m0 = mn0; m1 = mn1;

        float rs0 = 0.f, rs1 = 0.f;
        #pragma unroll
        for (int nt = 0; nt < 8; nt++) {
            S[nt][0] = __expf(S[nt][0] - mn0);
            S[nt][1] = __expf(S[nt][1] - mn0);
            S[nt][2] = __expf(S[nt][2] - mn1);
            S[nt][3] = __expf(S[nt][3] - mn1);
            rs0 += S[nt][0] + S[nt][1];
            rs1 += S[nt][2] + S[nt][3];
        }
        rs0 += __shfl_xor_sync(FULL, rs0, 1);
        rs0 += __shfl_xor_sync(FULL, rs0, 2);
        rs1 += __shfl_xor_sync(FULL, rs1, 1);
        rs1 += __shfl_xor_sync(FULL, rs1, 2);
        l0 = l0 * alpha0 + rs0;
        l1 = l1 * alpha1 + rs1;

        #pragma unroll
        for (int nt = 0; nt < 4; nt++) {
            O[nt][0] *= alpha0; O[nt][1] *= alpha0;
            O[nt][2] *= alpha1; O[nt][3] *= alpha1;
        }

        // ---- O += P V (fp16; A-frag = S regs, B-frag via ldmatrix.x4.trans)
        const int lrow = lane & 15;
        const int lcol = ((lane >> 4) & 1) * 8;
        #pragma unroll
        for (int kc = 0; kc < 4; kc++) {
            uint32_t a0 = pack_h2(S[2 * kc][0],     S[2 * kc][1]);
            uint32_t a1 = pack_h2(S[2 * kc][2],     S[2 * kc][3]);
            uint32_t a2 = pack_h2(S[2 * kc + 1][0], S[2 * kc + 1][1]);
            uint32_t a3 = pack_h2(S[2 * kc + 1][2], S[2 * kc + 1][3]);
            #pragma unroll
            for (int ntb = 0; ntb < 4; ntb += 2) {
                uint32_t r0, r1, r2, r3;
                uint32_t va = (uint32_t)__cvta_generic_to_shared(
                    &Vsm[s][kc * 16 + lrow][ntb * 8 + lcol]);
                ldsm_x4_t(r0, r1, r2, r3, va);
                mma_f16(O[ntb],     a0, a1, a2, a3, r0, r1);
                mma_f16(O[ntb + 1], a0, a1, a2, a3, r2, r3);
            }
        }
        __syncthreads();
    }

    // ---- epilogue: normalize, write g_attn[b][pos][head*32 + d] (fp32)
    const int b = bh >> 2, head = bh & 3;
    const float inv0 = 1.f / l0, inv1 = 1.f / l1;
    #pragma unroll
    for (int nt = 0; nt < 4; nt++) {
        int col = head * 32 + nt * 8 + 2 * tg;
        float2 w0 = make_float2(O[nt][0] * inv0, O[nt][1] * inv0);
        float2 w1 = make_float2(O[nt][2] * inv1, O[nt][3] * inv1);
        *(float2*)&g_attn[((size_t)b * NPOS + qrow0) * HIDDEN + col] = w0;
        *(float2*)&g_attn[((size_t)b * NPOS + qrow0 + 8) * HIDDEN + col] = w1;
    }
}

// ---------------------------------------------------------------------------
extern "C" void kernel_launch(void* const* d_in, const int* in_sizes, int n_in,
                              void* d_out, int out_size) {
    const float* x     = (const float*)d_in[0];
    const float* w_qkv = (const float*)d_in[1];
    const float* w_out = (const float*)d_in[2];
    const float* b_out = (const float*)d_in[3];
    float* y = (float*)d_out;

    gemm_tf32<CDIM, true, true><<<dim3(NPOS / 128, 384 / 64, BATCH), 256>>>(
        w_qkv, x, nullptr, nullptr);
    attn_mma_kernel<<<dim3(NPOS / 128, BATCH * HEADS), 256>>>();
    gemm_tf32<HIDDEN, false, false><<<dim3(NPOS / 128, CDIM / 64, BATCH), 256>>>(
        w_out, nullptr, b_out, y);
}

// round 6
// speedup vs baseline: 2.3030x; 1.1468x over previous
#include <cuda_runtime.h>
#include <cuda_fp16.h>
#include <cstdint>

#define HEADS 4
#define DIM_HEAD 32
#define NPOS 4096
#define BATCH 4
#define CDIM 256
#define HIDDEN 128
#define SCALE 0.17677669529663687f  // 32^-0.5
#define L2E 1.4426950408889634f

// Scratch (allocation-free rule: __device__ globals)
__device__ __align__(16) __half g_qh[BATCH * HEADS * NPOS * DIM_HEAD];
__device__ __align__(16) __half g_kh[BATCH * HEADS * NPOS * DIM_HEAD];
__device__ __align__(16) __half g_vh[BATCH * HEADS * NPOS * DIM_HEAD];
__device__ __align__(16) float  g_attn[BATCH * NPOS * HIDDEN];

// ---------------------------------------------------------------------------
// mma / ldmatrix / cp.async helpers
// ---------------------------------------------------------------------------
__device__ __forceinline__ uint32_t f2tf32(float x) {
    uint32_t u;
    asm("cvt.rna.tf32.f32 %0, %1;" : "=r"(u) : "f"(x));
    return u;
}

__device__ __forceinline__ void mma_tf32(float (&c)[4],
                                         uint32_t a0, uint32_t a1, uint32_t a2, uint32_t a3,
                                         uint32_t b0, uint32_t b1) {
    asm volatile(
        "mma.sync.aligned.m16n8k8.row.col.f32.tf32.tf32.f32 "
        "{%0,%1,%2,%3},{%4,%5,%6,%7},{%8,%9},{%0,%1,%2,%3};\n"
        : "+f"(c[0]), "+f"(c[1]), "+f"(c[2]), "+f"(c[3])
        : "r"(a0), "r"(a1), "r"(a2), "r"(a3), "r"(b0), "r"(b1));
}

__device__ __forceinline__ void mma_f16(float (&c)[4],
                                        uint32_t a0, uint32_t a1, uint32_t a2, uint32_t a3,
                                        uint32_t b0, uint32_t b1) {
    asm volatile(
        "mma.sync.aligned.m16n8k16.row.col.f32.f16.f16.f32 "
        "{%0,%1,%2,%3},{%4,%5,%6,%7},{%8,%9},{%0,%1,%2,%3};\n"
        : "+f"(c[0]), "+f"(c[1]), "+f"(c[2]), "+f"(c[3])
        : "r"(a0), "r"(a1), "r"(a2), "r"(a3), "r"(b0), "r"(b1));
}

__device__ __forceinline__ uint32_t pack_h2(float lo, float hi) {
    __half2 h = __floats2half2_rn(lo, hi);
    return *reinterpret_cast<uint32_t*>(&h);
}

__device__ __forceinline__ float fexp2(float x) {
    float r;
    asm("ex2.approx.f32 %0, %1;" : "=f"(r) : "f"(x));
    return r;
}

__device__ __forceinline__ void ldsm_x4(uint32_t& r0, uint32_t& r1,
                                        uint32_t& r2, uint32_t& r3, uint32_t addr) {
    asm volatile("ldmatrix.sync.aligned.m8n8.x4.shared.b16 {%0,%1,%2,%3}, [%4];"
                 : "=r"(r0), "=r"(r1), "=r"(r2), "=r"(r3) : "r"(addr));
}

__device__ __forceinline__ void ldsm_x4_t(uint32_t& r0, uint32_t& r1,
                                          uint32_t& r2, uint32_t& r3, uint32_t addr) {
    asm volatile("ldmatrix.sync.aligned.m8n8.x4.trans.shared.b16 {%0,%1,%2,%3}, [%4];"
                 : "=r"(r0), "=r"(r1), "=r"(r2), "=r"(r3) : "r"(addr));
}

__device__ __forceinline__ void cp16(uint32_t saddr, const void* gaddr) {
    asm volatile("cp.async.ca.shared.global [%0], [%1], 16;" :: "r"(saddr), "l"(gaddr));
}
__device__ __forceinline__ void cp_commit() { asm volatile("cp.async.commit_group;"); }
__device__ __forceinline__ void cp_wait1() { asm volatile("cp.async.wait_group 1;"); }
__device__ __forceinline__ void cp_wait0() { asm volatile("cp.async.wait_group 0;"); }

// ---------------------------------------------------------------------------
// Templated tf32-MMA GEMM for the two 1x1-conv projections. (unchanged R5)
// ---------------------------------------------------------------------------
template <int KDIM, bool BROWMAJOR_K, bool QKV_EPI>
__global__ __launch_bounds__(256) void gemm_tf32(const float* __restrict__ A,
                                                 const float* __restrict__ B,
                                                 const float* __restrict__ bias,
                                                 float* __restrict__ y) {
    __shared__ __align__(16) float As[16][72];
    __shared__ __align__(16) float Bs[16][136];
    const int b  = blockIdx.z;
    const int o0 = blockIdx.y * 64;
    const int p0 = blockIdx.x * 128;
    const int tid  = threadIdx.x;
    const int warp = tid >> 5, lane = tid & 31;
    const int g = lane >> 2, tg = lane & 3;
    const int wm = warp & 3, wn = warp >> 2;
    const int om = wm * 16, on = wn * 64;

    const float* Bb;
    if constexpr (BROWMAJOR_K) Bb = B + (size_t)b * KDIM * NPOS;
    else                       Bb = g_attn + (size_t)b * NPOS * HIDDEN;

    float C[8][4] = {};

    for (int k0 = 0; k0 < KDIM; k0 += 16) {
        {
            int oo = tid & 63, kq = tid >> 6;
            float4 wv = *(const float4*)&A[(size_t)(o0 + oo) * KDIM + k0 + kq * 4];
            As[kq * 4 + 0][oo] = __uint_as_float(f2tf32(wv.x));
            As[kq * 4 + 1][oo] = __uint_as_float(f2tf32(wv.y));
            As[kq * 4 + 2][oo] = __uint_as_float(f2tf32(wv.z));
            As[kq * 4 + 3][oo] = __uint_as_float(f2tf32(wv.w));
        }
        if constexpr (BROWMAJOR_K) {
            int kk = tid >> 5, pq = tid & 31;
            #pragma unroll
            for (int e = 0; e < 2; e++) {
                float4 xv = *(const float4*)&Bb[(size_t)(k0 + kk + e * 8) * NPOS + p0 + pq * 4];
                float4 tv;
                tv.x = __uint_as_float(f2tf32(xv.x));
                tv.y = __uint_as_float(f2tf32(xv.y));
                tv.z = __uint_as_float(f2tf32(xv.z));
                tv.w = __uint_as_float(f2tf32(xv.w));
                *(float4*)&Bs[kk + e * 8][pq * 4] = tv;
            }
        } else {
            int pp = tid & 127, kq = tid >> 7;
            #pragma unroll
            for (int e = 0; e < 2; e++) {
                int kq4 = (kq + 2 * e) * 4;
                float4 av = *(const float4*)&Bb[(size_t)(p0 + pp) * KDIM + k0 + kq4];
                Bs[kq4 + 0][pp] = __uint_as_float(f2tf32(av.x));
                Bs[kq4 + 1][pp] = __uint_as_float(f2tf32(av.y));
                Bs[kq4 + 2][pp] = __uint_as_float(f2tf32(av.z));
                Bs[kq4 + 3][pp] = __uint_as_float(f2tf32(av.w));
            }
        }
        __syncthreads();

        #pragma unroll
        for (int h = 0; h < 2; h++) {
            uint32_t a0 = __float_as_uint(As[h * 8 + tg][om + g]);
            uint32_t a1 = __float_as_uint(As[h * 8 + tg][om + g + 8]);
            uint32_t a2 = __float_as_uint(As[h * 8 + tg + 4][om + g]);
            uint32_t a3 = __float_as_uint(As[h * 8 + tg + 4][om + g + 8]);
            #pragma unroll
            for (int nt = 0; nt < 8; nt++) {
                int n = on + nt * 8 + g;
                uint32_t b0 = __float_as_uint(Bs[h * 8 + tg][n]);
                uint32_t b1 = __float_as_uint(Bs[h * 8 + tg + 4][n]);
                mma_tf32(C[nt], a0, a1, a2, a3, b0, b1);
            }
        }
        __syncthreads();
    }

    if constexpr (QKV_EPI) {
        __shared__ __align__(16) __half Stage[128][72];
        const float sc = (o0 < 128) ? SCALE : 1.0f;
        #pragma unroll
        for (int h = 0; h < 2; h++) {
            int orow = om + g + h * 8;
            #pragma unroll
            for (int nt = 0; nt < 8; nt++) {
                int p = on + nt * 8 + 2 * tg;
                Stage[p][orow]     = __float2half_rn(C[nt][2 * h] * sc);
                Stage[p + 1][orow] = __float2half_rn(C[nt][2 * h + 1] * sc);
            }
        }
        __syncthreads();
        int pp = tid >> 1, o_base = (tid & 1) * 32;
        int row0 = o0 + o_base;
        int part = row0 >> 7, head = (row0 & 127) >> 5;
        __half* dst = (part == 0) ? g_qh : (part == 1) ? g_kh : g_vh;
        size_t base = (((size_t)b * HEADS + head) * NPOS + p0 + pp) * DIM_HEAD;
        #pragma unroll
        for (int j = 0; j < 4; j++)
            *(uint4*)&dst[base + j * 8] = *(uint4*)&Stage[pp][o_base + j * 8];
    } else {
        #pragma unroll
        for (int h = 0; h < 2; h++) {
            int row = o0 + om + g + h * 8;
            float bb = bias[row];
            #pragma unroll
            for (int nt = 0; nt < 8; nt++) {
                int p = p0 + on + nt * 8 + 2 * tg;
                *(float2*)&y[((size_t)b * CDIM + row) * NPOS + p] =
                    make_float2(C[nt][2 * h] + bb, C[nt][2 * h + 1] + bb);
            }
        }
    }
}

// ---------------------------------------------------------------------------
// Flash attention, fp16, M=32 rows per warp (two m16 row-blocks sharing
// K/V fragment loads). Block = 4 warps = 128 q-rows. Key tile = 64.
// K b-frags via ldmatrix.x4; V via ldmatrix.x4.trans; l via ones-B mma.
// ---------------------------------------------------------------------------
#define KVSTR 40   // halves per row (80B)
#define ONES_H2 0x3C003C00u

__global__ __launch_bounds__(128) void attn_mma_kernel() {
    __shared__ __align__(16) __half Ksm[2][64][KVSTR];
    __shared__ __align__(16) __half Vsm[2][64][KVSTR];

    const int bh = blockIdx.y;
    const int q0 = blockIdx.x * 128;
    const int tid = threadIdx.x;
    const int warp = tid >> 5, lane = tid & 31;
    const int g = lane >> 2, tg = lane & 3;
    const unsigned FULL = 0xffffffffu;

    const __half* Qh = g_qh + (size_t)bh * NPOS * DIM_HEAD;
    const __half* Kh = g_kh + (size_t)bh * NPOS * DIM_HEAD;
    const __half* Vh = g_vh + (size_t)bh * NPOS * DIM_HEAD;

    // Q A-fragments for both row-blocks (fp16 m16n8k16), rows qrA(+8), qrB(+8)
    const int qrA = q0 + warp * 32 + g;
    const int qrB = qrA + 16;
    uint32_t QfA[2][4], QfB[2][4];
    #pragma unroll
    for (int kc = 0; kc < 2; kc++) {
        int c = kc * 16 + 2 * tg;
        QfA[kc][0] = *(const uint32_t*)&Qh[(size_t)qrA * DIM_HEAD + c];
        QfA[kc][1] = *(const uint32_t*)&Qh[(size_t)(qrA + 8) * DIM_HEAD + c];
        QfA[kc][2] = *(const uint32_t*)&Qh[(size_t)qrA * DIM_HEAD + c + 8];
        QfA[kc][3] = *(const uint32_t*)&Qh[(size_t)(qrA + 8) * DIM_HEAD + c + 8];
        QfB[kc][0] = *(const uint32_t*)&Qh[(size_t)qrB * DIM_HEAD + c];
        QfB[kc][1] = *(const uint32_t*)&Qh[(size_t)(qrB + 8) * DIM_HEAD + c];
        QfB[kc][2] = *(const uint32_t*)&Qh[(size_t)qrB * DIM_HEAD + c + 8];
        QfB[kc][3] = *(const uint32_t*)&Qh[(size_t)(qrB + 8) * DIM_HEAD + c + 8];
    }

    // cp.async loader: 128 threads, each covers 32B of one row (2 cp16)
    const int kr  = tid >> 1;            // row 0..63
    const int kc8 = (tid & 1) * 16;      // half-offset 0 or 16
    uint32_t kdst[2], vdst[2];
    #pragma unroll
    for (int s = 0; s < 2; s++) {
        kdst[s] = (uint32_t)__cvta_generic_to_shared(&Ksm[s][kr][kc8]);
        vdst[s] = (uint32_t)__cvta_generic_to_shared(&Vsm[s][kr][kc8]);
    }

    // prologue: tile 0 -> buffer 0
    cp16(kdst[0],      Kh + (size_t)kr * DIM_HEAD + kc8);
    cp16(kdst[0] + 16, Kh + (size_t)kr * DIM_HEAD + kc8 + 8);
    cp16(vdst[0],      Vh + (size_t)kr * DIM_HEAD + kc8);
    cp16(vdst[0] + 16, Vh + (size_t)kr * DIM_HEAD + kc8 + 8);
    cp_commit();

    float OA[4][4] = {}, OB[4][4] = {};
    float ClA[4] = {}, ClB[4] = {};
    float mA0 = -1e30f, mA1 = -1e30f, mB0 = -1e30f, mB1 = -1e30f;

    // ldmatrix addresses (loop-invariant)
    const int klrow = lane & 7, kld8 = (lane >> 3) * 8;
    const int vlrow = lane & 15, vlcol = ((lane >> 4) & 1) * 8;

    for (int it = 0; it < NPOS / 64; it++) {
        const int s = it & 1;
        if (it + 1 < NPOS / 64) {
            const __half* kb = Kh + ((size_t)(it + 1) * 64 + kr) * DIM_HEAD + kc8;
            const __half* vb = Vh + ((size_t)(it + 1) * 64 + kr) * DIM_HEAD + kc8;
            cp16(kdst[s ^ 1],      kb);
            cp16(kdst[s ^ 1] + 16, kb + 8);
            cp16(vdst[s ^ 1],      vb);
            cp16(vdst[s ^ 1] + 16, vb + 8);
            cp_commit();
            cp_wait1();
        } else {
            cp_wait0();
        }
        __syncthreads();

        // ---- K b-fragments: one ldmatrix.x4 per n-tile (covers both k-chunks)
        uint32_t Kf[8][4];
        #pragma unroll
        for (int nt = 0; nt < 8; nt++) {
            uint32_t a = (uint32_t)__cvta_generic_to_shared(
                &Ksm[s][nt * 8 + klrow][kld8]);
            ldsm_x4(Kf[nt][0], Kf[nt][1], Kf[nt][2], Kf[nt][3], a);
        }

        float S[8][4];
        uint32_t PA[4][4], PB[4][4];

        // ================= row-block A =================
        #pragma unroll
        for (int nt = 0; nt < 8; nt++) {
            S[nt][0] = S[nt][1] = S[nt][2] = S[nt][3] = 0.f;
            mma_f16(S[nt], QfA[0][0], QfA[0][1], QfA[0][2], QfA[0][3], Kf[nt][0], Kf[nt][1]);
            mma_f16(S[nt], QfA[1][0], QfA[1][1], QfA[1][2], QfA[1][3], Kf[nt][2], Kf[nt][3]);
        }
        {
            float r0 = -1e30f, r1 = -1e30f;
            #pragma unroll
            for (int nt = 0; nt < 8; nt++) {
                r0 = fmaxf(r0, fmaxf(S[nt][0], S[nt][1]));
                r1 = fmaxf(r1, fmaxf(S[nt][2], S[nt][3]));
            }
            r0 = fmaxf(r0, __shfl_xor_sync(FULL, r0, 1));
            r0 = fmaxf(r0, __shfl_xor_sync(FULL, r0, 2));
            r1 = fmaxf(r1, __shfl_xor_sync(FULL, r1, 1));
            r1 = fmaxf(r1, __shfl_xor_sync(FULL, r1, 2));
            float mn0 = fmaxf(mA0, r0), mn1 = fmaxf(mA1, r1);
            float al0 = fexp2((mA0 - mn0) * L2E), al1 = fexp2((mA1 - mn1) * L2E);
            mA0 = mn0; mA1 = mn1;
            float mnl0 = mn0 * L2E, mnl1 = mn1 * L2E;
            #pragma unroll
            for (int nt = 0; nt < 8; nt++) {
                S[nt][0] = fexp2(fmaf(S[nt][0], L2E, -mnl0));
                S[nt][1] = fexp2(fmaf(S[nt][1], L2E, -mnl0));
                S[nt][2] = fexp2(fmaf(S[nt][2], L2E, -mnl1));
                S[nt][3] = fexp2(fmaf(S[nt][3], L2E, -mnl1));
            }
            #pragma unroll
            for (int kc = 0; kc < 4; kc++) {
                PA[kc][0] = pack_h2(S[2 * kc][0],     S[2 * kc][1]);
                PA[kc][1] = pack_h2(S[2 * kc][2],     S[2 * kc][3]);
                PA[kc][2] = pack_h2(S[2 * kc + 1][0], S[2 * kc + 1][1]);
                PA[kc][3] = pack_h2(S[2 * kc + 1][2], S[2 * kc + 1][3]);
            }
            #pragma unroll
            for (int nt = 0; nt < 4; nt++) {
                OA[nt][0] *= al0; OA[nt][1] *= al0;
                OA[nt][2] *= al1; OA[nt][3] *= al1;
            }
            ClA[0] *= al0; ClA[2] *= al1;
        }

        // ================= row-block B (reuses S regs, K frags) =================
        #pragma unroll
        for (int nt = 0; nt < 8; nt++) {
            S[nt][0] = S[nt][1] = S[nt][2] = S[nt][3] = 0.f;
            mma_f16(S[nt], QfB[0][0], QfB[0][1], QfB[0][2], QfB[0][3], Kf[nt][0], Kf[nt][1]);
            mma_f16(S[nt], QfB[1][0], QfB[1][1], QfB[1][2], QfB[1][3], Kf[nt][2], Kf[nt][3]);
        }
        {
            float r0 = -1e30f, r1 = -1e30f;
            #pragma unroll
            for (int nt = 0; nt < 8; nt++) {
                r0 = fmaxf(r0, fmaxf(S[nt][0], S[nt][1]));
                r1 = fmaxf(r1, fmaxf(S[nt][2], S[nt][3]));
            }
            r0 = fmaxf(r0, __shfl_xor_sync(FULL, r0, 1));
            r0 = fmaxf(r0, __shfl_xor_sync(FULL, r0, 2));
            r1 = fmaxf(r1, __shfl_xor_sync(FULL, r1, 1));
            r1 = fmaxf(r1, __shfl_xor_sync(FULL, r1, 2));
            float mn0 = fmaxf(mB0, r0), mn1 = fmaxf(mB1, r1);
            float al0 = fexp2((mB0 - mn0) * L2E), al1 = fexp2((mB1 - mn1) * L2E);
            mB0 = mn0; mB1 = mn1;
            float mnl0 = mn0 * L2E, mnl1 = mn1 * L2E;
            #pragma unroll
            for (int nt = 0; nt < 8; nt++) {
                S[nt][0] = fexp2(fmaf(S[nt][0], L2E, -mnl0));
                S[nt][1] = fexp2(fmaf(S[nt][1], L2E, -mnl0));
                S[nt][2] = fexp2(fmaf(S[nt][2], L2E, -mnl1));
                S[nt][3] = fexp2(fmaf(S[nt][3], L2E, -mnl1));
            }
            #pragma unroll
            for (int kc = 0; kc < 4; kc++) {
                PB[kc][0] = pack_h2(S[2 * kc][0],     S[2 * kc][1]);
                PB[kc][1] = pack_h2(S[2 * kc][2],     S[2 * kc][3]);
                PB[kc][2] = pack_h2(S[2 * kc + 1][0], S[2 * kc + 1][1]);
                PB[kc][3] = pack_h2(S[2 * kc + 1][2], S[2 * kc + 1][3]);
            }
            #pragma unroll
            for (int nt = 0; nt < 4; nt++) {
                OB[nt][0] *= al0; OB[nt][1] *= al0;
                OB[nt][2] *= al1; OB[nt][3] *= al1;
            }
            ClB[0] *= al0; ClB[2] *= al1;
        }

        // ---- PV for both row-blocks; V frags loaded once
        #pragma unroll
        for (int kc = 0; kc < 4; kc++) {
            uint32_t r0, r1, r2, r3;
            uint32_t va0 = (uint32_t)__cvta_generic_to_shared(
                &Vsm[s][kc * 16 + vlrow][vlcol]);
            ldsm_x4_t(r0, r1, r2, r3, va0);
            mma_f16(OA[0], PA[kc][0], PA[kc][1], PA[kc][2], PA[kc][3], r0, r1);
            mma_f16(OA[1], PA[kc][0], PA[kc][1], PA[kc][2], PA[kc][3], r2, r3);
            mma_f16(OB[0], PB[kc][0], PB[kc][1], PB[kc][2], PB[kc][3], r0, r1);
            mma_f16(OB[1], PB[kc][0], PB[kc][1], PB[kc][2], PB[kc][3], r2, r3);
            uint32_t va1 = (uint32_t)__cvta_generic_to_shared(
                &Vsm[s][kc * 16 + vlrow][16 + vlcol]);
            ldsm_x4_t(r0, r1, r2, r3, va1);
            mma_f16(OA[2], PA[kc][0], PA[kc][1], PA[kc][2], PA[kc][3], r0, r1);
            mma_f16(OA[3], PA[kc][0], PA[kc][1], PA[kc][2], PA[kc][3], r2, r3);
            mma_f16(OB[2], PB[kc][0], PB[kc][1], PB[kc][2], PB[kc][3], r0, r1);
            mma_f16(OB[3], PB[kc][0], PB[kc][1], PB[kc][2], PB[kc][3], r2, r3);
            // l accumulation: ones B-frag => row sums of P land in every lane
            mma_f16(ClA, PA[kc][0], PA[kc][1], PA[kc][2], PA[kc][3], ONES_H2, ONES_H2);
            mma_f16(ClB, PB[kc][0], PB[kc][1], PB[kc][2], PB[kc][3], ONES_H2, ONES_H2);
        }
        __syncthreads();
    }

    // ---- epilogue: normalize, write g_attn[b][pos][head*32 + d]
    const int b = bh >> 2, head = bh & 3;
    const float iA0 = 1.f / ClA[0], iA1 = 1.f / ClA[2];
    const float iB0 = 1.f / ClB[0], iB1 = 1.f / ClB[2];
    #pragma unroll
    for (int nt = 0; nt < 4; nt++) {
        int col = head * 32 + nt * 8 + 2 * tg;
        *(float2*)&g_attn[((size_t)b * NPOS + qrA) * HIDDEN + col] =
            make_float2(OA[nt][0] * iA0, OA[nt][1] * iA0);
        *(float2*)&g_attn[((size_t)b * NPOS + qrA + 8) * HIDDEN + col] =
            make_float2(OA[nt][2] * iA1, OA[nt][3] * iA1);
        *(float2*)&g_attn[((size_t)b * NPOS + qrB) * HIDDEN + col] =
            make_float2(OB[nt][0] * iB0, OB[nt][1] * iB0);
        *(float2*)&g_attn[((size_t)b * NPOS + qrB + 8) * HIDDEN + col] =
            make_float2(OB[nt][2] * iB1, OB[nt][3] * iB1);
    }
}

// ---------------------------------------------------------------------------
extern "C" void kernel_launch(void* const* d_in, const int* in_sizes, int n_in,
                              void* d_out, int out_size) {
    const float* x     = (const float*)d_in[0];
    const float* w_qkv = (const float*)d_in[1];
    const float* w_out = (const float*)d_in[2];
    const float* b_out = (const float*)d_in[3];
    float* y = (float*)d_out;

    gemm_tf32<CDIM, true, true><<<dim3(NPOS / 128, 384 / 64, BATCH), 256>>>(
        w_qkv, x, nullptr, nullptr);
    attn_mma_kernel<<<dim3(NPOS / 128, BATCH * HEADS), 128>>>();
    gemm_tf32<HIDDEN, false, false><<<dim3(NPOS / 128, CDIM / 64, BATCH), 256>>>(
        w_out, nullptr, b_out, y);
}

// round 7
// speedup vs baseline: 2.8186x; 1.2239x over previous
#include <cuda_runtime.h>
#include <cuda_fp16.h>
#include <cstdint>

#define HEADS 4
#define DIM_HEAD 32
#define NPOS 4096
#define BATCH 4
#define CDIM 256
#define HIDDEN 128
#define SCALE 0.17677669529663687f  // 32^-0.5
#define L2E 1.4426950408889634f

// Scratch (allocation-free rule: __device__ globals)
__device__ __align__(16) __half g_qh[BATCH * HEADS * NPOS * DIM_HEAD];
__device__ __align__(16) __half g_kh[BATCH * HEADS * NPOS * DIM_HEAD];
__device__ __align__(16) __half g_vh[BATCH * HEADS * NPOS * DIM_HEAD];
__device__ __align__(16) float  g_attn[BATCH * NPOS * HIDDEN];
__device__ __align__(16) __half g_xh[BATCH * CDIM * NPOS];
__device__ __align__(16) __half g_wqh[384 * CDIM];

// ---------------------------------------------------------------------------
// helpers
// ---------------------------------------------------------------------------
__device__ __forceinline__ uint32_t f2tf32(float x) {
    uint32_t u;
    asm("cvt.rna.tf32.f32 %0, %1;" : "=r"(u) : "f"(x));
    return u;
}

__device__ __forceinline__ void mma_tf32(float (&c)[4],
                                         uint32_t a0, uint32_t a1, uint32_t a2, uint32_t a3,
                                         uint32_t b0, uint32_t b1) {
    asm volatile(
        "mma.sync.aligned.m16n8k8.row.col.f32.tf32.tf32.f32 "
        "{%0,%1,%2,%3},{%4,%5,%6,%7},{%8,%9},{%0,%1,%2,%3};\n"
        : "+f"(c[0]), "+f"(c[1]), "+f"(c[2]), "+f"(c[3])
        : "r"(a0), "r"(a1), "r"(a2), "r"(a3), "r"(b0), "r"(b1));
}

__device__ __forceinline__ void mma_f16(float (&c)[4],
                                        uint32_t a0, uint32_t a1, uint32_t a2, uint32_t a3,
                                        uint32_t b0, uint32_t b1) {
    asm volatile(
        "mma.sync.aligned.m16n8k16.row.col.f32.f16.f16.f32 "
        "{%0,%1,%2,%3},{%4,%5,%6,%7},{%8,%9},{%0,%1,%2,%3};\n"
        : "+f"(c[0]), "+f"(c[1]), "+f"(c[2]), "+f"(c[3])
        : "r"(a0), "r"(a1), "r"(a2), "r"(a3), "r"(b0), "r"(b1));
}

__device__ __forceinline__ uint32_t pack_h2(float lo, float hi) {
    __half2 h = __floats2half2_rn(lo, hi);
    return *reinterpret_cast<uint32_t*>(&h);
}

__device__ __forceinline__ float fexp2(float x) {
    float r;
    asm("ex2.approx.f32 %0, %1;" : "=f"(r) : "f"(x));
    return r;
}

__device__ __forceinline__ uint32_t h2exp2(uint32_t x) {
    uint32_t r;
    asm("ex2.approx.f16x2 %0, %1;" : "=r"(r) : "r"(x));
    return r;
}

__device__ __forceinline__ void ldsm_x4(uint32_t& r0, uint32_t& r1,
                                        uint32_t& r2, uint32_t& r3, uint32_t addr) {
    asm volatile("ldmatrix.sync.aligned.m8n8.x4.shared.b16 {%0,%1,%2,%3}, [%4];"
                 : "=r"(r0), "=r"(r1), "=r"(r2), "=r"(r3) : "r"(addr));
}

__device__ __forceinline__ void ldsm_x4_t(uint32_t& r0, uint32_t& r1,
                                          uint32_t& r2, uint32_t& r3, uint32_t addr) {
    asm volatile("ldmatrix.sync.aligned.m8n8.x4.trans.shared.b16 {%0,%1,%2,%3}, [%4];"
                 : "=r"(r0), "=r"(r1), "=r"(r2), "=r"(r3) : "r"(addr));
}

__device__ __forceinline__ void cp16(uint32_t saddr, const void* gaddr) {
    asm volatile("cp.async.ca.shared.global [%0], [%1], 16;" :: "r"(saddr), "l"(gaddr));
}
__device__ __forceinline__ void cp_commit() { asm volatile("cp.async.commit_group;"); }
__device__ __forceinline__ void cp_wait1() { asm volatile("cp.async.wait_group 1;"); }
__device__ __forceinline__ void cp_wait0() { asm volatile("cp.async.wait_group 0;"); }

// ---------------------------------------------------------------------------
// fp32 -> fp16 bulk convert (float4 -> 2x half2)
// ---------------------------------------------------------------------------
__global__ __launch_bounds__(256) void f2h_kernel(const float* __restrict__ src,
                                                  __half* __restrict__ dst, int n4) {
    int i = blockIdx.x * blockDim.x + threadIdx.x;
    if (i < n4) {
        float4 v = ((const float4*)src)[i];
        ((uint2*)dst)[i] = make_uint2(pack_h2(v.x, v.y), pack_h2(v.z, v.w));
    }
}

// ---------------------------------------------------------------------------
// QKV projection, all-fp16 MMA, cp.async double-buffered.
//  C[o][p] = sum_k wq[o][k] * x[b][k][p];   o-tile 64, p-tile 128, k-step 32.
// A-frags via ldmatrix.x4 (As[o][k], stride 40h); B via ldmatrix.x4.trans
// (Bs[k][p], stride 136h). Epilogue: fp16 scatter to g_{q,k,v}h via smem stage.
// ---------------------------------------------------------------------------
__global__ __launch_bounds__(256) void qkv_h_kernel() {
    __shared__ __align__(16) __half As[2][64][40];
    __shared__ __align__(16) __half Bs[2][32][136];
    __shared__ __align__(16) __half Stage[128][72];

    const int b  = blockIdx.z;
    const int o0 = blockIdx.y * 64;
    const int p0 = blockIdx.x * 128;
    const int tid  = threadIdx.x;
    const int warp = tid >> 5, lane = tid & 31;
    const int g = lane >> 2, tg = lane & 3;
    const int wm = warp & 3, wn = warp >> 2;
    const int om = wm * 16, on = wn * 64;

    const __half* Wg = g_wqh;
    const __half* Xg = g_xh + (size_t)b * CDIM * NPOS;

    // loader mapping
    const int ar = tid >> 2, ac = (tid & 3) * 8;           // A: 64 x 32
    const int br = tid >> 3, bc = (tid & 7) * 16;          // B: 32 x 128 (2 cp16)
    uint32_t adst[2], bdst[2];
    #pragma unroll
    for (int s = 0; s < 2; s++) {
        adst[s] = (uint32_t)__cvta_generic_to_shared(&As[s][ar][ac]);
        bdst[s] = (uint32_t)__cvta_generic_to_shared(&Bs[s][br][bc]);
    }

    // prologue: k0 = 0 -> buffer 0
    cp16(adst[0], Wg + (size_t)(o0 + ar) * CDIM + ac);
    cp16(bdst[0],      Xg + (size_t)br * NPOS + p0 + bc);
    cp16(bdst[0] + 16, Xg + (size_t)br * NPOS + p0 + bc + 8);
    cp_commit();

    float C[8][4] = {};

    // ldmatrix addresses (loop-invariant parts)
    const int alrow = lane & 15, alc8 = (lane >> 4) * 8;

    for (int it = 0; it < CDIM / 32; it++) {
        const int s = it & 1;
        if (it + 1 < CDIM / 32) {
            int k0 = (it + 1) * 32;
            cp16(adst[s ^ 1], Wg + (size_t)(o0 + ar) * CDIM + k0 + ac);
            cp16(bdst[s ^ 1],      Xg + (size_t)(k0 + br) * NPOS + p0 + bc);
            cp16(bdst[s ^ 1] + 16, Xg + (size_t)(k0 + br) * NPOS + p0 + bc + 8);
            cp_commit();
            cp_wait1();
        } else {
            cp_wait0();
        }
        __syncthreads();

        #pragma unroll
        for (int kc = 0; kc < 2; kc++) {
            uint32_t a0, a1, a2, a3;
            uint32_t aa = (uint32_t)__cvta_generic_to_shared(
                &As[s][om + alrow][kc * 16 + alc8]);
            ldsm_x4(a0, a1, a2, a3, aa);
            #pragma unroll
            for (int pt = 0; pt < 4; pt++) {
                uint32_t r0, r1, r2, r3;
                uint32_t ba = (uint32_t)__cvta_generic_to_shared(
                    &Bs[s][kc * 16 + alrow][on + pt * 16 + alc8]);
                ldsm_x4_t(r0, r1, r2, r3, ba);
                mma_f16(C[pt * 2],     a0, a1, a2, a3, r0, r1);
                mma_f16(C[pt * 2 + 1], a0, a1, a2, a3, r2, r3);
            }
        }
        __syncthreads();
    }

    // epilogue: scatter via smem stage, coalesced 16B half stores
    const float sc = (o0 < 128) ? SCALE : 1.0f;
    #pragma unroll
    for (int h = 0; h < 2; h++) {
        int orow = om + g + h * 8;
        #pragma unroll
        for (int nt = 0; nt < 8; nt++) {
            int p = on + nt * 8 + 2 * tg;
            Stage[p][orow]     = __float2half_rn(C[nt][2 * h] * sc);
            Stage[p + 1][orow] = __float2half_rn(C[nt][2 * h + 1] * sc);
        }
    }
    __syncthreads();
    int pp = tid >> 1, o_base = (tid & 1) * 32;
    int row0 = o0 + o_base;
    int part = row0 >> 7, head = (row0 & 127) >> 5;
    __half* dst = (part == 0) ? g_qh : (part == 1) ? g_kh : g_vh;
    size_t base = (((size_t)b * HEADS + head) * NPOS + p0 + pp) * DIM_HEAD;
    #pragma unroll
    for (int j = 0; j < 4; j++)
        *(uint4*)&dst[base + j * 8] = *(uint4*)&Stage[pp][o_base + j * 8];
}

// ---------------------------------------------------------------------------
// Output projection, tf32 (unchanged R6 structure; B = g_attn [p][k]).
// ---------------------------------------------------------------------------
__global__ __launch_bounds__(256) void proj_tf32(const float* __restrict__ A,
                                                 const float* __restrict__ bias,
                                                 float* __restrict__ y) {
    __shared__ __align__(16) float As[16][72];
    __shared__ __align__(16) float Bs[16][136];
    const int b  = blockIdx.z;
    const int o0 = blockIdx.y * 64;
    const int p0 = blockIdx.x * 128;
    const int tid  = threadIdx.x;
    const int warp = tid >> 5, lane = tid & 31;
    const int g = lane >> 2, tg = lane & 3;
    const int wm = warp & 3, wn = warp >> 2;
    const int om = wm * 16, on = wn * 64;

    const float* Bb = g_attn + (size_t)b * NPOS * HIDDEN;

    float C[8][4] = {};

    for (int k0 = 0; k0 < HIDDEN; k0 += 16) {
        {
            int oo = tid & 63, kq = tid >> 6;
            float4 wv = *(const float4*)&A[(size_t)(o0 + oo) * HIDDEN + k0 + kq * 4];
            As[kq * 4 + 0][oo] = __uint_as_float(f2tf32(wv.x));
            As[kq * 4 + 1][oo] = __uint_as_float(f2tf32(wv.y));
            As[kq * 4 + 2][oo] = __uint_as_float(f2tf32(wv.z));
            As[kq * 4 + 3][oo] = __uint_as_float(f2tf32(wv.w));
        }
        {
            int pp = tid & 127, kq = tid >> 7;
            #pragma unroll
            for (int e = 0; e < 2; e++) {
                int kq4 = (kq + 2 * e) * 4;
                float4 av = *(const float4*)&Bb[(size_t)(p0 + pp) * HIDDEN + k0 + kq4];
                Bs[kq4 + 0][pp] = __uint_as_float(f2tf32(av.x));
                Bs[kq4 + 1][pp] = __uint_as_float(f2tf32(av.y));
                Bs[kq4 + 2][pp] = __uint_as_float(f2tf32(av.z));
                Bs[kq4 + 3][pp] = __uint_as_float(f2tf32(av.w));
            }
        }
        __syncthreads();

        #pragma unroll
        for (int h = 0; h < 2; h++) {
            uint32_t a0 = __float_as_uint(As[h * 8 + tg][om + g]);
            uint32_t a1 = __float_as_uint(As[h * 8 + tg][om + g + 8]);
            uint32_t a2 = __float_as_uint(As[h * 8 + tg + 4][om + g]);
            uint32_t a3 = __float_as_uint(As[h * 8 + tg + 4][om + g + 8]);
            #pragma unroll
            for (int nt = 0; nt < 8; nt++) {
                int n = on + nt * 8 + g;
                uint32_t b0 = __float_as_uint(Bs[h * 8 + tg][n]);
                uint32_t b1 = __float_as_uint(Bs[h * 8 + tg + 4][n]);
                mma_tf32(C[nt], a0, a1, a2, a3, b0, b1);
            }
        }
        __syncthreads();
    }

    #pragma unroll
    for (int h = 0; h < 2; h++) {
        int row = o0 + om + g + h * 8;
        float bb = bias[row];
        #pragma unroll
        for (int nt = 0; nt < 8; nt++) {
            int p = p0 + on + nt * 8 + 2 * tg;
            *(float2*)&y[((size_t)b * CDIM + row) * NPOS + p] =
                make_float2(C[nt][2 * h] + bb, C[nt][2 * h + 1] + bb);
        }
    }
}

// ---------------------------------------------------------------------------
// Flash attention, fp16, M=32 rows per warp, ex2.approx.f16x2 softmax.
// Block = 4 warps = 128 q-rows. Key tile = 64. l via ones-B mma.
// ---------------------------------------------------------------------------
#define KVSTR 40   // halves per row (80B)
#define ONES_H2 0x3C003C00u

__global__ __launch_bounds__(128) void attn_mma_kernel() {
    __shared__ __align__(16) __half Ksm[2][64][KVSTR];
    __shared__ __align__(16) __half Vsm[2][64][KVSTR];

    const int bh = blockIdx.y;
    const int q0 = blockIdx.x * 128;
    const int tid = threadIdx.x;
    const int warp = tid >> 5, lane = tid & 31;
    const int g = lane >> 2, tg = lane & 3;
    const unsigned FULL = 0xffffffffu;

    const __half* Qh = g_qh + (size_t)bh * NPOS * DIM_HEAD;
    const __half* Kh = g_kh + (size_t)bh * NPOS * DIM_HEAD;
    const __half* Vh = g_vh + (size_t)bh * NPOS * DIM_HEAD;

    const int qrA = q0 + warp * 32 + g;
    const int qrB = qrA + 16;
    uint32_t QfA[2][4], QfB[2][4];
    #pragma unroll
    for (int kc = 0; kc < 2; kc++) {
        int c = kc * 16 + 2 * tg;
        QfA[kc][0] = *(const uint32_t*)&Qh[(size_t)qrA * DIM_HEAD + c];
        QfA[kc][1] = *(const uint32_t*)&Qh[(size_t)(qrA + 8) * DIM_HEAD + c];
        QfA[kc][2] = *(const uint32_t*)&Qh[(size_t)qrA * DIM_HEAD + c + 8];
        QfA[kc][3] = *(const uint32_t*)&Qh[(size_t)(qrA + 8) * DIM_HEAD + c + 8];
        QfB[kc][0] = *(const uint32_t*)&Qh[(size_t)qrB * DIM_HEAD + c];
        QfB[kc][1] = *(const uint32_t*)&Qh[(size_t)(qrB + 8) * DIM_HEAD + c];
        QfB[kc][2] = *(const uint32_t*)&Qh[(size_t)qrB * DIM_HEAD + c + 8];
        QfB[kc][3] = *(const uint32_t*)&Qh[(size_t)(qrB + 8) * DIM_HEAD + c + 8];
    }

    const int kr  = tid >> 1;
    const int kc8 = (tid & 1) * 16;
    uint32_t kdst[2], vdst[2];
    #pragma unroll
    for (int s = 0; s < 2; s++) {
        kdst[s] = (uint32_t)__cvta_generic_to_shared(&Ksm[s][kr][kc8]);
        vdst[s] = (uint32_t)__cvta_generic_to_shared(&Vsm[s][kr][kc8]);
    }

    cp16(kdst[0],      Kh + (size_t)kr * DIM_HEAD + kc8);
    cp16(kdst[0] + 16, Kh + (size_t)kr * DIM_HEAD + kc8 + 8);
    cp16(vdst[0],      Vh + (size_t)kr * DIM_HEAD + kc8);
    cp16(vdst[0] + 16, Vh + (size_t)kr * DIM_HEAD + kc8 + 8);
    cp_commit();

    float OA[4][4] = {}, OB[4][4] = {};
    float ClA[4] = {}, ClB[4] = {};
    float mA0 = -1e30f, mA1 = -1e30f, mB0 = -1e30f, mB1 = -1e30f;

    const int klrow = lane & 7, kld8 = (lane >> 3) * 8;
    const int vlrow = lane & 15, vlcol = ((lane >> 4) & 1) * 8;

    for (int it = 0; it < NPOS / 64; it++) {
        const int s = it & 1;
        if (it + 1 < NPOS / 64) {
            const __half* kb = Kh + ((size_t)(it + 1) * 64 + kr) * DIM_HEAD + kc8;
            const __half* vb = Vh + ((size_t)(it + 1) * 64 + kr) * DIM_HEAD + kc8;
            cp16(kdst[s ^ 1],      kb);
            cp16(kdst[s ^ 1] + 16, kb + 8);
            cp16(vdst[s ^ 1],      vb);
            cp16(vdst[s ^ 1] + 16, vb + 8);
            cp_commit();
            cp_wait1();
        } else {
            cp_wait0();
        }
        __syncthreads();

        uint32_t Kf[8][4];
        #pragma unroll
        for (int nt = 0; nt < 8; nt++) {
            uint32_t a = (uint32_t)__cvta_generic_to_shared(
                &Ksm[s][nt * 8 + klrow][kld8]);
            ldsm_x4(Kf[nt][0], Kf[nt][1], Kf[nt][2], Kf[nt][3], a);
        }

        float S[8][4];
        uint32_t PA[4][4], PB[4][4];

        // ================= row-block A =================
        #pragma unroll
        for (int nt = 0; nt < 8; nt++) {
            S[nt][0] = S[nt][1] = S[nt][2] = S[nt][3] = 0.f;
            mma_f16(S[nt], QfA[0][0], QfA[0][1], QfA[0][2], QfA[0][3], Kf[nt][0], Kf[nt][1]);
            mma_f16(S[nt], QfA[1][0], QfA[1][1], QfA[1][2], QfA[1][3], Kf[nt][2], Kf[nt][3]);
        }
        {
            float r0 = -1e30f, r1 = -1e30f;
            #pragma unroll
            for (int nt = 0; nt < 8; nt++) {
                r0 = fmaxf(r0, fmaxf(S[nt][0], S[nt][1]));
                r1 = fmaxf(r1, fmaxf(S[nt][2], S[nt][3]));
            }
            r0 = fmaxf(r0, __shfl_xor_sync(FULL, r0, 1));
            r0 = fmaxf(r0, __shfl_xor_sync(FULL, r0, 2));
            r1 = fmaxf(r1, __shfl_xor_sync(FULL, r1, 1));
            r1 = fmaxf(r1, __shfl_xor_sync(FULL, r1, 2));
            float mn0 = fmaxf(mA0, r0), mn1 = fmaxf(mA1, r1);
            float al0 = fexp2((mA0 - mn0) * L2E), al1 = fexp2((mA1 - mn1) * L2E);
            mA0 = mn0; mA1 = mn1;
            float mnl0 = mn0 * L2E, mnl1 = mn1 * L2E;
            #pragma unroll
            for (int kc = 0; kc < 4; kc++) {
                PA[kc][0] = h2exp2(pack_h2(fmaf(S[2*kc][0], L2E, -mnl0),
                                           fmaf(S[2*kc][1], L2E, -mnl0)));
                PA[kc][1] = h2exp2(pack_h2(fmaf(S[2*kc][2], L2E, -mnl1),
                                           fmaf(S[2*kc][3], L2E, -mnl1)));
                PA[kc][2] = h2exp2(pack_h2(fmaf(S[2*kc+1][0], L2E, -mnl0),
                                           fmaf(S[2*kc+1][1], L2E, -mnl0)));
                PA[kc][3] = h2exp2(pack_h2(fmaf(S[2*kc+1][2], L2E, -mnl1),
                                           fmaf(S[2*kc+1][3], L2E, -mnl1)));
            }
            #pragma unroll
            for (int nt = 0; nt < 4; nt++) {
                OA[nt][0] *= al0; OA[nt][1] *= al0;
                OA[nt][2] *= al1; OA[nt][3] *= al1;
            }
            ClA[0] *= al0; ClA[2] *= al1;
        }

        // ================= row-block B =================
        #pragma unroll
        for (int nt = 0; nt < 8; nt++) {
            S[nt][0] = S[nt][1] = S[nt][2] = S[nt][3] = 0.f;
            mma_f16(S[nt], QfB[0][0], QfB[0][1], QfB[0][2], QfB[0][3], Kf[nt][0], Kf[nt][1]);
            mma_f16(S[nt], QfB[1][0], QfB[1][1], QfB[1][2], QfB[1][3], Kf[nt][2], Kf[nt][3]);
        }
        {
            float r0 = -1e30f, r1 = -1e30f;
            #pragma unroll
            for (int nt = 0; nt < 8; nt++) {
                r0 = fmaxf(r0, fmaxf(S[nt][0], S[nt][1]));
                r1 = fmaxf(r1, fmaxf(S[nt][2], S[nt][3]));
            }
            r0 = fmaxf(r0, __shfl_xor_sync(FULL, r0, 1));
            r0 = fmaxf(r0, __shfl_xor_sync(FULL, r0, 2));
            r1 = fmaxf(r1, __shfl_xor_sync(FULL, r1, 1));
            r1 = fmaxf(r1, __shfl_xor_sync(FULL, r1, 2));
            float mn0 = fmaxf(mB0, r0), mn1 = fmaxf(mB1, r1);
            float al0 = fexp2((mB0 - mn0) * L2E), al1 = fexp2((mB1 - mn1) * L2E);
            mB0 = mn0; mB1 = mn1;
            float mnl0 = mn0 * L2E, mnl1 = mn1 * L2E;
            #pragma unroll
            for (int kc = 0; kc < 4; kc++) {
                PB[kc][0] = h2exp2(pack_h2(fmaf(S[2*kc][0], L2E, -mnl0),
                                           fmaf(S[2*kc][1], L2E, -mnl0)));
                PB[kc][1] = h2exp2(pack_h2(fmaf(S[2*kc][2], L2E, -mnl1),
                                           fmaf(S[2*kc][3], L2E, -mnl1)));
                PB[kc][2] = h2exp2(pack_h2(fmaf(S[2*kc+1][0], L2E, -mnl0),
                                           fmaf(S[2*kc+1][1], L2E, -mnl0)));
                PB[kc][3] = h2exp2(pack_h2(fmaf(S[2*kc+1][2], L2E, -mnl1),
                                           fmaf(S[2*kc+1][3], L2E, -mnl1)));
            }
            #pragma unroll
            for (int nt = 0; nt < 4; nt++) {
                OB[nt][0] *= al0; OB[nt][1] *= al0;
                OB[nt][2] *= al1; OB[nt][3] *= al1;
            }
            ClB[0] *= al0; ClB[2] *= al1;
        }

        // ---- PV for both row-blocks; V frags loaded once
        #pragma unroll
        for (int kc = 0; kc < 4; kc++) {
            uint32_t r0, r1, r2, r3;
            uint32_t va0 = (uint32_t)__cvta_generic_to_shared(
                &Vsm[s][kc * 16 + vlrow][vlcol]);
            ldsm_x4_t(r0, r1, r2, r3, va0);
            mma_f16(OA[0], PA[kc][0], PA[kc][1], PA[kc][2], PA[kc][3], r0, r1);
            mma_f16(OA[1], PA[kc][0], PA[kc][1], PA[kc][2], PA[kc][3], r2, r3);
            mma_f16(OB[0], PB[kc][0], PB[kc][1], PB[kc][2], PB[kc][3], r0, r1);
            mma_f16(OB[1], PB[kc][0], PB[kc][1], PB[kc][2], PB[kc][3], r2, r3);
            uint32_t va1 = (uint32_t)__cvta_generic_to_shared(
                &Vsm[s][kc * 16 + vlrow][16 + vlcol]);
            ldsm_x4_t(r0, r1, r2, r3, va1);
            mma_f16(OA[2], PA[kc][0], PA[kc][1], PA[kc][2], PA[kc][3], r0, r1);
            mma_f16(OA[3], PA[kc][0], PA[kc][1], PA[kc][2], PA[kc][3], r2, r3);
            mma_f16(OB[2], PB[kc][0], PB[kc][1], PB[kc][2], PB[kc][3], r0, r1);
            mma_f16(OB[3], PB[kc][0], PB[kc][1], PB[kc][2], PB[kc][3], r2, r3);
            mma_f16(ClA, PA[kc][0], PA[kc][1], PA[kc][2], PA[kc][3], ONES_H2, ONES_H2);
            mma_f16(ClB, PB[kc][0], PB[kc][1], PB[kc][2], PB[kc][3], ONES_H2, ONES_H2);
        }
        __syncthreads();
    }

    const int b = bh >> 2, head = bh & 3;
    const float iA0 = 1.f / ClA[0], iA1 = 1.f / ClA[2];
    const float iB0 = 1.f / ClB[0], iB1 = 1.f / ClB[2];
    #pragma unroll
    for (int nt = 0; nt < 4; nt++) {
        int col = head * 32 + nt * 8 + 2 * tg;
        *(float2*)&g_attn[((size_t)b * NPOS + qrA) * HIDDEN + col] =
            make_float2(OA[nt][0] * iA0, OA[nt][1] * iA0);
        *(float2*)&g_attn[((size_t)b * NPOS + qrA + 8) * HIDDEN + col] =
            make_float2(OA[nt][2] * iA1, OA[nt][3] * iA1);
        *(float2*)&g_attn[((size_t)b * NPOS + qrB) * HIDDEN + col] =
            make_float2(OB[nt][0] * iB0, OB[nt][1] * iB0);
        *(float2*)&g_attn[((size_t)b * NPOS + qrB + 8) * HIDDEN + col] =
            make_float2(OB[nt][2] * iB1, OB[nt][3] * iB1);
    }
}

// ---------------------------------------------------------------------------
extern "C" void kernel_launch(void* const* d_in, const int* in_sizes, int n_in,
                              void* d_out, int out_size) {
    const float* x     = (const float*)d_in[0];
    const float* w_qkv = (const float*)d_in[1];
    const float* w_out = (const float*)d_in[2];
    const float* b_out = (const float*)d_in[3];
    float* y = (float*)d_out;

    __half* d_xh;  cudaGetSymbolAddress((void**)&d_xh,  g_xh);
    __half* d_wqh; cudaGetSymbolAddress((void**)&d_wqh, g_wqh);

    f2h_kernel<<<(BATCH * CDIM * NPOS / 4 + 255) / 256, 256>>>(x, d_xh,
                                                               BATCH * CDIM * NPOS / 4);
    f2h_kernel<<<(384 * CDIM / 4 + 255) / 256, 256>>>(w_qkv, d_wqh, 384 * CDIM / 4);
    qkv_h_kernel<<<dim3(NPOS / 128, 384 / 64, BATCH), 256>>>();
    attn_mma_kernel<<<dim3(NPOS / 128, BATCH * HEADS), 128>>>();
    proj_tf32<<<dim3(NPOS / 128, CDIM / 64, BATCH), 256>>>(w_out, b_out, y);
}